// round 9
// baseline (speedup 1.0000x reference)
#include <cuda_runtime.h>
#include <cuda_bf16.h>
#include <cstdint>

// RecentAttention: N=500000, B=10000 sessions x L=50, H=128.
// K1: g_a[s] = x[last_ixs[s]] @ W1^T + b1 + b2      (bf16 mma.sync, 157 CTAs)
// K2: persistent, 512 thr, 2 CTAs/SM, M=256 tile (4 sessions, 200 valid rows):
//     C = (0.5x)@W2^T + onehot(sess)@(0.5a)^T  via 8+1 k16 mma steps
//     e_row = qb + sum_c 0.5 q_c + sum_c 0.5 q_c * tanh(C)  -> softmax -> pool

#define SA 136                  // smem row stride (bf16 elems), conflict-free
#define NTILE2 2500             // 4 sessions per tile

__device__ float g_a[10000 * 128];

__device__ __forceinline__ void st4bf(__nv_bfloat16* p, float4 v) {
    *(__nv_bfloat162*)p       = __floats2bfloat162_rn(v.x, v.y);
    *(__nv_bfloat162*)(p + 2) = __floats2bfloat162_rn(v.z, v.w);
}

#define MMA16816(C, A, B0, B1)                                              \
    asm volatile("mma.sync.aligned.m16n8k16.row.col.f32.bf16.bf16.f32 "    \
        "{%0,%1,%2,%3}, {%4,%5,%6,%7}, {%8,%9}, {%0,%1,%2,%3};"            \
        : "+f"((C)[0]), "+f"((C)[1]), "+f"((C)[2]), "+f"((C)[3])           \
        : "r"((A)[0]), "r"((A)[1]), "r"((A)[2]), "r"((A)[3]),              \
          "r"(B0), "r"(B1))

#define LDSM4(R, a)                                                         \
    asm volatile("ldmatrix.sync.aligned.m8n8.x4.shared.b16 {%0,%1,%2,%3}, [%4];" \
        : "=r"((R)[0]), "=r"((R)[1]), "=r"((R)[2]), "=r"((R)[3]) : "r"(a))

// ---------------- K1: a[s] = x[last]@W1^T + b1 + b2 (proven R6 path) -------
__device__ __forceinline__ void mma_pass32(uint32_t abase, uint32_t bbase,
                                           float c[2][4][4]) {
    #pragma unroll
    for (int ks = 0; ks < 8; ks++) {
        uint32_t A0[4], A1[4], B0[4], B1[4];
        LDSM4(A0, abase + ks * 32);
        LDSM4(A1, abase + 16 * SA * 2 + ks * 32);
        LDSM4(B0, bbase + ks * 32);
        LDSM4(B1, bbase + 16 * SA * 2 + ks * 32);
        MMA16816(c[0][0], A0, B0[0], B0[1]);
        MMA16816(c[0][1], A0, B0[2], B0[3]);
        MMA16816(c[0][2], A0, B1[0], B1[1]);
        MMA16816(c[0][3], A0, B1[2], B1[3]);
        MMA16816(c[1][0], A1, B0[0], B0[1]);
        MMA16816(c[1][1], A1, B0[2], B0[3]);
        MMA16816(c[1][2], A1, B1[0], B1[1]);
        MMA16816(c[1][3], A1, B1[2], B1[3]);
    }
}

__global__ void __launch_bounds__(256, 1) k1_abias(
    const float* __restrict__ x, const float* __restrict__ W1,
    const float* __restrict__ b1, const float* __restrict__ b2,
    const int* __restrict__ last_ixs)
{
    extern __shared__ char smraw[];
    __nv_bfloat16* Asm = (__nv_bfloat16*)smraw;
    __nv_bfloat16* Wsm = (__nv_bfloat16*)(smraw + 34816);
    int*   li = (int*)(smraw + 69632);
    float* bs = (float*)(smraw + 70144);

    int tid = threadIdx.x, warp = tid >> 5, lane = tid & 31;
    int base = blockIdx.x * 64;
    int valid = min(64, 10000 - base);

    if (tid < 128) {
        li[tid] = (tid < valid) ? last_ixs[base + tid] : 0;
        bs[tid] = b1[tid] + b2[tid];
    }
    #pragma unroll
    for (int j = 0; j < 16; j++) {
        int f4 = tid + j * 256, row = f4 >> 5, c4 = f4 & 31;
        st4bf(Wsm + row * SA + c4 * 4, ((const float4*)W1)[f4]);
    }
    __syncthreads();
    #pragma unroll
    for (int j = 0; j < 16; j++) {
        int f4 = tid + j * 256, row = f4 >> 5, c4 = f4 & 31;
        float4 v = make_float4(0.f, 0.f, 0.f, 0.f);
        if (row < valid) v = ((const float4*)(x + (size_t)li[row] * 128))[c4];
        st4bf(Asm + row * SA + c4 * 4, v);
    }
    __syncthreads();

    int mw = warp >> 1, m0 = mw * 32;
    int q = lane >> 3, r7 = lane & 7;
    uint32_t asm_u = (uint32_t)__cvta_generic_to_shared(Asm);
    uint32_t wsm_u = (uint32_t)__cvta_generic_to_shared(Wsm);
    uint32_t abase = asm_u + 2 * ((m0 + (q & 1) * 8 + r7) * SA + (q >> 1) * 8);

    #pragma unroll
    for (int p = 0; p < 2; p++) {
        int n0 = (warp & 1) * 64 + p * 32;
        uint32_t bbase = wsm_u + 2 * ((n0 + (q >> 1) * 8 + r7) * SA + (q & 1) * 8);
        float c[2][4][4] = {};
        mma_pass32(abase, bbase, c);
        #pragma unroll
        for (int mi = 0; mi < 2; mi++)
            #pragma unroll
            for (int ni = 0; ni < 4; ni++) {
                int col = n0 + ni * 8 + (lane & 3) * 2;
                #pragma unroll
                for (int r2 = 0; r2 < 2; r2++) {
                    int row = m0 + mi * 16 + (lane >> 2) + 8 * r2;
                    if (row < valid) {
                        size_t o = (size_t)(base + row) * 128 + col;
                        g_a[o]     = c[mi][ni][2 * r2]     + bs[col];
                        g_a[o + 1] = c[mi][ni][2 * r2 + 1] + bs[col + 1];
                    }
                }
            }
    }
}

// ---------------- K2: persistent, M=256, bias folded into GEMM ----------------
// smem: Wsm@0(34816) Asm@34816(69632) Wext@104448(4096: 128 cols x 16 k bf16)
//       qh@108544(512) e_part@109056(2048) alpha@111104(1024)  total 112128
#define K2_SMEM 112128

__global__ void __launch_bounds__(512, 2) k2_main(
    const float* __restrict__ x, const float* __restrict__ W2,
    const float* __restrict__ q, const float* __restrict__ qbp,
    float* __restrict__ out)
{
    extern __shared__ char smraw[];
    __nv_bfloat16* Wsm  = (__nv_bfloat16*)smraw;
    __nv_bfloat16* Asm  = (__nv_bfloat16*)(smraw + 34816);
    __nv_bfloat16* Wext = (__nv_bfloat16*)(smraw + 104448);
    float* qh_sm  = (float*)(smraw + 108544);
    float* e_part = (float*)(smraw + 109056);   // [2][256]
    float* alpha  = (float*)(smraw + 111104);   // [200]

    int tid = threadIdx.x, warp = tid >> 5, lane = tid & 31;
    int m0 = (warp >> 1) * 32;                  // warp: 32 rows x 64 cols
    int n0 = (warp & 1) * 64;
    int qq = lane >> 3, r7 = lane & 7;
    float qb = qbp[0];

    #pragma unroll
    for (int j = 0; j < 8; j++) {               // W2 -> bf16 smem (once)
        int f4 = tid + j * 512, row = f4 >> 5, c4 = f4 & 31;
        st4bf(Wsm + row * SA + c4 * 4, ((const float4*)W2)[f4]);
    }
    #pragma unroll
    for (int j = 0; j < 34; j++)                // zero Asm (pad rows stay 0)
        ((uint32_t*)Asm)[tid + j * 512] = 0u;
    #pragma unroll
    for (int j = 0; j < 2; j++)                 // zero Wext (k=4..15 stay 0)
        ((uint32_t*)Wext)[tid + j * 512] = 0u;
    if (tid < 128) qh_sm[tid] = 0.5f * q[tid];
    __syncthreads();

    uint32_t asm_u  = (uint32_t)__cvta_generic_to_shared(Asm);
    uint32_t wsm_u  = (uint32_t)__cvta_generic_to_shared(Wsm);
    uint32_t wext_u = (uint32_t)__cvta_generic_to_shared(Wext);
    uint32_t abase = asm_u + 2 * ((m0 + (qq & 1) * 8 + r7) * SA + (qq >> 1) * 8);
    uint32_t bbase = wsm_u + 2 * ((n0 + (qq >> 1) * 8 + r7) * SA + (qq & 1) * 8);
    // Wext rows = 16 bf16 = 32 bytes
    uint32_t ebase = wext_u + (n0 + (qq >> 1) * 8 + r7) * 32 + (qq & 1) * 16;

    // one-hot session-indicator A fragments (loop-invariant, k=0..3 used)
    int klo = (lane & 3) * 2;
    uint32_t Aext[2][4];
    #pragma unroll
    for (int mi = 0; mi < 2; mi++) {
        #pragma unroll
        for (int h = 0; h < 2; h++) {           // h=0: row, h=1: row+8
            int row = m0 + mi * 16 + (lane >> 2) + 8 * h;
            int sess = (row < 50) ? 0 : (row < 100) ? 1 : (row < 150) ? 2
                     : (row < 200) ? 3 : -1;
            uint32_t v = 0;
            if (sess == klo)     v |= 0x3F80u;
            if (sess == klo + 1) v |= 0x3F800000u;
            Aext[mi][h] = v;
        }
        Aext[mi][2] = 0u; Aext[mi][3] = 0u;     // k=8..15
    }

    float csum = 0.f;                           // sum of 0.5*q over warp's cols
    #pragma unroll
    for (int g = 0; g < 16; g++) {
        float4 qv = *(const float4*)(qh_sm + n0 + g * 4);
        csum += qv.x + qv.y + qv.z + qv.w;
    }

    for (int t = blockIdx.x; t < NTILE2; t += gridDim.x) {
        const float* xt = x + (size_t)t * 25600;       // 200 rows x 128

        // ---- fill: 0.5*x -> bf16 Asm ; 0.5*a -> bf16 Wext ----
        float4 v[13];
        #pragma unroll
        for (int j = 0; j < 13; j++) {
            int f4 = tid + j * 512;
            if (f4 < 6400) v[j] = ((const float4*)xt)[f4];
        }
        float av = 0.5f * g_a[(size_t)t * 512 + tid];  // j=tid>>7, col=tid&127
        #pragma unroll
        for (int j = 0; j < 13; j++) {
            int f4 = tid + j * 512;
            if (f4 < 6400) {
                float4 w = v[j];
                w.x *= 0.5f; w.y *= 0.5f; w.z *= 0.5f; w.w *= 0.5f;
                st4bf(Asm + (f4 >> 5) * SA + (f4 & 31) * 4, w);
            }
        }
        Wext[(tid & 127) * 16 + (tid >> 7)] = __float2bfloat16(av);
        __syncthreads();                                // operands ready

        // ---- MMA: C = (0.5x)@W2^T + onehot@(0.5a)^T ----
        float c[2][8][4] = {};
        #pragma unroll
        for (int ks = 0; ks < 8; ks++) {
            uint32_t A0[4], A1[4], B0[4], B1[4], B2[4], B3[4];
            LDSM4(A0, abase + ks * 32);
            LDSM4(A1, abase + 16 * SA * 2 + ks * 32);
            LDSM4(B0, bbase + ks * 32);
            LDSM4(B1, bbase + 16 * SA * 2 + ks * 32);
            LDSM4(B2, bbase + 32 * SA * 2 + ks * 32);
            LDSM4(B3, bbase + 48 * SA * 2 + ks * 32);
            MMA16816(c[0][0], A0, B0[0], B0[1]); MMA16816(c[1][0], A1, B0[0], B0[1]);
            MMA16816(c[0][1], A0, B0[2], B0[3]); MMA16816(c[1][1], A1, B0[2], B0[3]);
            MMA16816(c[0][2], A0, B1[0], B1[1]); MMA16816(c[1][2], A1, B1[0], B1[1]);
            MMA16816(c[0][3], A0, B1[2], B1[3]); MMA16816(c[1][3], A1, B1[2], B1[3]);
            MMA16816(c[0][4], A0, B2[0], B2[1]); MMA16816(c[1][4], A1, B2[0], B2[1]);
            MMA16816(c[0][5], A0, B2[2], B2[3]); MMA16816(c[1][5], A1, B2[2], B2[3]);
            MMA16816(c[0][6], A0, B3[0], B3[1]); MMA16816(c[1][6], A1, B3[0], B3[1]);
            MMA16816(c[0][7], A0, B3[2], B3[3]); MMA16816(c[1][7], A1, B3[2], B3[3]);
        }
        {   // 9th k-step: bias
            uint32_t B0[4], B1[4], B2[4], B3[4];
            LDSM4(B0, ebase);
            LDSM4(B1, ebase + 16 * 32);
            LDSM4(B2, ebase + 32 * 32);
            LDSM4(B3, ebase + 48 * 32);
            MMA16816(c[0][0], Aext[0], B0[0], B0[1]); MMA16816(c[1][0], Aext[1], B0[0], B0[1]);
            MMA16816(c[0][1], Aext[0], B0[2], B0[3]); MMA16816(c[1][1], Aext[1], B0[2], B0[3]);
            MMA16816(c[0][2], Aext[0], B1[0], B1[1]); MMA16816(c[1][2], Aext[1], B1[0], B1[1]);
            MMA16816(c[0][3], Aext[0], B1[2], B1[3]); MMA16816(c[1][3], Aext[1], B1[2], B1[3]);
            MMA16816(c[0][4], Aext[0], B2[0], B2[1]); MMA16816(c[1][4], Aext[1], B2[0], B2[1]);
            MMA16816(c[0][5], Aext[0], B2[2], B2[3]); MMA16816(c[1][5], Aext[1], B2[2], B2[3]);
            MMA16816(c[0][6], Aext[0], B3[0], B3[1]); MMA16816(c[1][6], Aext[1], B3[0], B3[1]);
            MMA16816(c[0][7], Aext[0], B3[2], B3[3]); MMA16816(c[1][7], Aext[1], B3[2], B3[3]);
        }

        // ---- epilogue: e partials = sum 0.5*q*tanh(C) ----
        float pe[2][2] = {};
        #pragma unroll
        for (int ni = 0; ni < 8; ni++) {
            int col = n0 + ni * 8 + (lane & 3) * 2;
            float q0 = qh_sm[col], q1 = qh_sm[col + 1];
            #pragma unroll
            for (int mi = 0; mi < 2; mi++)
                #pragma unroll
                for (int r2 = 0; r2 < 2; r2++) {
                    int row = m0 + mi * 16 + (lane >> 2) + 8 * r2;
                    if (row < 200) {
                        float t0, t1;
                        asm("tanh.approx.f32 %0, %1;" : "=f"(t0) : "f"(c[mi][ni][2 * r2]));
                        asm("tanh.approx.f32 %0, %1;" : "=f"(t1) : "f"(c[mi][ni][2 * r2 + 1]));
                        pe[mi][r2] = fmaf(q0, t0, fmaf(q1, t1, pe[mi][r2]));
                    }
                }
        }
        #pragma unroll
        for (int mi = 0; mi < 2; mi++)
            #pragma unroll
            for (int r2 = 0; r2 < 2; r2++) {
                float vv = pe[mi][r2];
                vv += __shfl_xor_sync(0xffffffffu, vv, 1);
                vv += __shfl_xor_sync(0xffffffffu, vv, 2);
                if ((lane & 3) == 0) {
                    int row = m0 + mi * 16 + (lane >> 2) + 8 * r2;
                    e_part[(warp & 1) * 256 + row] = vv + csum;
                }
            }
        __syncthreads();

        // ---- per-session softmax over 50 rows (warps 0..3) ----
        if (warp < 4) {
            int rb = warp * 50;
            int i1 = rb + lane;
            bool v2 = lane < 18;
            int i2 = rb + 32 + lane;
            float e1 = e_part[i1] + e_part[256 + i1] + qb;
            float e2 = v2 ? (e_part[i2] + e_part[256 + i2] + qb) : -1e30f;
            float m = fmaxf(e1, e2);
            #pragma unroll
            for (int o = 16; o; o >>= 1) m = fmaxf(m, __shfl_xor_sync(0xffffffffu, m, o));
            float z1 = __expf(e1 - m);
            float z2 = v2 ? __expf(e2 - m) : 0.f;
            float s = z1 + z2;
            #pragma unroll
            for (int o = 16; o; o >>= 1) s += __shfl_xor_sync(0xffffffffu, s, o);
            float inv = __frcp_rn(s);
            alpha[i1] = z1 * inv;
            if (v2) alpha[i2] = z2 * inv;
        }
        __syncthreads();

        // ---- pooling: out[4t+s][col] = sum_j alpha_j * x_j[col] (fp32, L2) ----
        int s = tid >> 7, col = tid & 127;
        const float* xr = xt + s * 6400 + col;
        const float* al = alpha + s * 50;
        float acc = 0.f;
        #pragma unroll 10
        for (int j = 0; j < 50; j++) acc = fmaf(al[j], xr[j * 128], acc);
        out[(size_t)(4 * t + s) * 128 + col] = acc;
    }
}

extern "C" void kernel_launch(void* const* d_in, const int* in_sizes, int n_in,
                              void* d_out, int out_size)
{
    const float* x   = (const float*)d_in[0];
    const float* W1w = (const float*)d_in[1];
    const float* W1b = (const float*)d_in[2];
    const float* W2w = (const float*)d_in[3];
    const float* W2b = (const float*)d_in[4];
    const float* qw  = (const float*)d_in[5];
    const float* qb  = (const float*)d_in[6];
    const int* last  = (const int*)d_in[8];
    float* out = (float*)d_out;

    int smem1 = 70656;
    cudaFuncSetAttribute(k1_abias, cudaFuncAttributeMaxDynamicSharedMemorySize, smem1);
    cudaFuncSetAttribute(k2_main,  cudaFuncAttributeMaxDynamicSharedMemorySize, K2_SMEM);

    int nsm = 148;
    cudaDeviceGetAttribute(&nsm, cudaDevAttrMultiProcessorCount, 0);

    k1_abias<<<157, 256, smem1>>>(x, W1w, W1b, W2b, last);
    k2_main<<<2 * nsm, 512, K2_SMEM>>>(x, W2w, qw, qb, out);
}

// round 11
// speedup vs baseline: 2.5850x; 2.5850x over previous
#include <cuda_runtime.h>
#include <cuda_bf16.h>
#include <cstdint>

// RecentAttention: N=500000, B=10000 sessions x L=50, H=128.
// K1: g_a[s] = x[last_ixs[s]] @ W1^T + b1 + b2      (bf16 mma.sync, 157 CTAs)
// K2: persistent, 1 CTA x 512 thr per SM, cp.async double-buffered x tile:
//     C = (0.5x)@W2^T + onehot(sess)@(0.5a)^T  (8+1 k16 mma steps, 32x32 warp tiles)
//     e = qb + sum 0.5q + sum 0.5q*tanh(C) ; per-session softmax ; pool from smem.

#define SA 136                  // smem row stride (bf16 elems), conflict-free
#define NTILE2 5000             // 2 sessions (100 rows) per tile

__device__ float g_a[10000 * 128];

__device__ __forceinline__ void st4bf(__nv_bfloat16* p, float4 v) {
    *(__nv_bfloat162*)p       = __floats2bfloat162_rn(v.x, v.y);
    *(__nv_bfloat162*)(p + 2) = __floats2bfloat162_rn(v.z, v.w);
}

#define MMA16816(C, A, B0, B1)                                              \
    asm volatile("mma.sync.aligned.m16n8k16.row.col.f32.bf16.bf16.f32 "    \
        "{%0,%1,%2,%3}, {%4,%5,%6,%7}, {%8,%9}, {%0,%1,%2,%3};"            \
        : "+f"((C)[0]), "+f"((C)[1]), "+f"((C)[2]), "+f"((C)[3])           \
        : "r"((A)[0]), "r"((A)[1]), "r"((A)[2]), "r"((A)[3]),              \
          "r"(B0), "r"(B1))

#define LDSM4(R, a)                                                         \
    asm volatile("ldmatrix.sync.aligned.m8n8.x4.shared.b16 {%0,%1,%2,%3}, [%4];" \
        : "=r"((R)[0]), "=r"((R)[1]), "=r"((R)[2]), "=r"((R)[3]) : "r"(a))

// ---------------- K1: a[s] = x[last]@W1^T + b1 + b2 (proven R6 path) -------
__device__ __forceinline__ void mma_pass32(uint32_t abase, uint32_t bbase,
                                           float c[2][4][4]) {
    #pragma unroll
    for (int ks = 0; ks < 8; ks++) {
        uint32_t A0[4], A1[4], B0[4], B1[4];
        LDSM4(A0, abase + ks * 32);
        LDSM4(A1, abase + 16 * SA * 2 + ks * 32);
        LDSM4(B0, bbase + ks * 32);
        LDSM4(B1, bbase + 16 * SA * 2 + ks * 32);
        MMA16816(c[0][0], A0, B0[0], B0[1]);
        MMA16816(c[0][1], A0, B0[2], B0[3]);
        MMA16816(c[0][2], A0, B1[0], B1[1]);
        MMA16816(c[0][3], A0, B1[2], B1[3]);
        MMA16816(c[1][0], A1, B0[0], B0[1]);
        MMA16816(c[1][1], A1, B0[2], B0[3]);
        MMA16816(c[1][2], A1, B1[0], B1[1]);
        MMA16816(c[1][3], A1, B1[2], B1[3]);
    }
}

__global__ void __launch_bounds__(256, 1) k1_abias(
    const float* __restrict__ x, const float* __restrict__ W1,
    const float* __restrict__ b1, const float* __restrict__ b2,
    const int* __restrict__ last_ixs)
{
    extern __shared__ char smraw[];
    __nv_bfloat16* Asm = (__nv_bfloat16*)smraw;
    __nv_bfloat16* Wsm = (__nv_bfloat16*)(smraw + 34816);
    int*   li = (int*)(smraw + 69632);
    float* bs = (float*)(smraw + 70144);

    int tid = threadIdx.x, warp = tid >> 5, lane = tid & 31;
    int base = blockIdx.x * 64;
    int valid = min(64, 10000 - base);

    if (tid < 128) {
        li[tid] = (tid < valid) ? last_ixs[base + tid] : 0;
        bs[tid] = b1[tid] + b2[tid];
    }
    #pragma unroll
    for (int j = 0; j < 16; j++) {
        int f4 = tid + j * 256, row = f4 >> 5, c4 = f4 & 31;
        st4bf(Wsm + row * SA + c4 * 4, ((const float4*)W1)[f4]);
    }
    __syncthreads();
    #pragma unroll
    for (int j = 0; j < 16; j++) {
        int f4 = tid + j * 256, row = f4 >> 5, c4 = f4 & 31;
        float4 v = make_float4(0.f, 0.f, 0.f, 0.f);
        if (row < valid) v = ((const float4*)(x + (size_t)li[row] * 128))[c4];
        st4bf(Asm + row * SA + c4 * 4, v);
    }
    __syncthreads();

    int mw = warp >> 1, m0 = mw * 32;
    int q = lane >> 3, r7 = lane & 7;
    uint32_t asm_u = (uint32_t)__cvta_generic_to_shared(Asm);
    uint32_t wsm_u = (uint32_t)__cvta_generic_to_shared(Wsm);
    uint32_t abase = asm_u + 2 * ((m0 + (q & 1) * 8 + r7) * SA + (q >> 1) * 8);

    #pragma unroll
    for (int p = 0; p < 2; p++) {
        int n0 = (warp & 1) * 64 + p * 32;
        uint32_t bbase = wsm_u + 2 * ((n0 + (q >> 1) * 8 + r7) * SA + (q & 1) * 8);
        float c[2][4][4] = {};
        mma_pass32(abase, bbase, c);
        #pragma unroll
        for (int mi = 0; mi < 2; mi++)
            #pragma unroll
            for (int ni = 0; ni < 4; ni++) {
                int col = n0 + ni * 8 + (lane & 3) * 2;
                #pragma unroll
                for (int r2 = 0; r2 < 2; r2++) {
                    int row = m0 + mi * 16 + (lane >> 2) + 8 * r2;
                    if (row < valid) {
                        size_t o = (size_t)(base + row) * 128 + col;
                        g_a[o]     = c[mi][ni][2 * r2]     + bs[col];
                        g_a[o + 1] = c[mi][ni][2 * r2 + 1] + bs[col + 1];
                    }
                }
            }
    }
}

// ---------------- K2: persistent 512-thread CTA, cp.async pipeline --------
// smem: xf0@0(51200) xf1@51200(51200) Wsm@102400(34816) Asm@137216(34816)
//       Wext@172032(4096) qh@176128(512) e_part@176640(2048) alpha@178688(512)
#define K2_SMEM 179200

__global__ void __launch_bounds__(512, 1) k2_main(
    const float* __restrict__ x, const float* __restrict__ W2,
    const float* __restrict__ q, const float* __restrict__ qbp,
    float* __restrict__ out)
{
    extern __shared__ char smraw[];
    float* xf[2] = { (float*)smraw, (float*)(smraw + 51200) };
    __nv_bfloat16* Wsm  = (__nv_bfloat16*)(smraw + 102400);
    __nv_bfloat16* Asm  = (__nv_bfloat16*)(smraw + 137216);
    __nv_bfloat16* Wext = (__nv_bfloat16*)(smraw + 172032);
    float* qh_sm  = (float*)(smraw + 176128);
    float* e_part = (float*)(smraw + 176640);   // [4][128]
    float* alpha  = (float*)(smraw + 178688);   // [100]

    int tid = threadIdx.x, warp = tid >> 5, lane = tid & 31;
    int m0 = (warp & 3) * 32;                   // warp tile: 32 rows x 32 cols
    int n0 = (warp >> 2) * 32;
    int qq = lane >> 3, r7 = lane & 7;
    float qb = qbp[0];

    #pragma unroll
    for (int j = 0; j < 8; j++) {               // W2 -> bf16 smem (once)
        int f4 = tid + j * 512, row = f4 >> 5, c4 = f4 & 31;
        st4bf(Wsm + row * SA + c4 * 4, ((const float4*)W2)[f4]);
    }
    #pragma unroll
    for (int j = 0; j < 17; j++) {              // zero Asm (pad rows stay 0)
        int i = tid + j * 512;
        if (i < 8704) ((uint32_t*)Asm)[i] = 0u;
    }
    #pragma unroll
    for (int j = 0; j < 2; j++)                 // zero Wext (k>=2 stay 0)
        ((uint32_t*)Wext)[tid + j * 512] = 0u;
    if (tid < 128) qh_sm[tid] = 0.5f * q[tid];
    __syncthreads();                            // R10 BUG FIX: qh_sm visible
                                                // before csum reads below

    uint32_t asm_u  = (uint32_t)__cvta_generic_to_shared(Asm);
    uint32_t wsm_u  = (uint32_t)__cvta_generic_to_shared(Wsm);
    uint32_t wext_u = (uint32_t)__cvta_generic_to_shared(Wext);
    uint32_t abase = asm_u + 2 * ((m0 + (qq & 1) * 8 + r7) * SA + (qq >> 1) * 8);
    uint32_t bbase = wsm_u + 2 * ((n0 + (qq >> 1) * 8 + r7) * SA + (qq & 1) * 8);
    uint32_t ebase = wext_u + (n0 + (qq >> 1) * 8 + r7) * 32 + (qq & 1) * 16;

    // one-hot session-indicator A fragments (k=0 -> sess0, k=1 -> sess1)
    int klo = (lane & 3) * 2;
    uint32_t Aext[2][4];
    #pragma unroll
    for (int mi = 0; mi < 2; mi++) {
        #pragma unroll
        for (int h = 0; h < 2; h++) {
            int row = m0 + mi * 16 + (lane >> 2) + 8 * h;
            int sess = (row < 50) ? 0 : (row < 100) ? 1 : -1;
            uint32_t v = 0;
            if (sess == klo)     v |= 0x3F80u;
            if (sess == klo + 1) v |= 0x3F800000u;
            Aext[mi][h] = v;
        }
        Aext[mi][2] = 0u; Aext[mi][3] = 0u;
    }

    float csum = 0.f;                           // sum of 0.5*q over warp's cols
    #pragma unroll
    for (int g = 0; g < 8; g++) {
        float4 qv = *(const float4*)(qh_sm + n0 + g * 4);
        csum += qv.x + qv.y + qv.z + qv.w;
    }

    // prefetch first tile into xf0
    {
        const float* xt = x + (size_t)blockIdx.x * 12800;
        #pragma unroll
        for (int j = 0; j < 7; j++) {
            int f4 = tid + j * 512;
            if (f4 < 3200) {
                uint32_t d = (uint32_t)__cvta_generic_to_shared(xf[0] + f4 * 4);
                asm volatile("cp.async.cg.shared.global [%0], [%1], 16;"
                             :: "r"(d), "l"(xt + f4 * 4) : "memory");
            }
        }
        asm volatile("cp.async.commit_group;" ::: "memory");
    }

    int it = 0;
    for (int t = blockIdx.x; t < NTILE2; t += gridDim.x, it++) {
        float* xfb = xf[it & 1];
        asm volatile("cp.async.wait_group 0;" ::: "memory");
        __syncthreads();                        // tile data visible to all

        // prefetch next tile into other buffer
        int tn = t + gridDim.x;
        if (tn < NTILE2) {
            const float* xt2 = x + (size_t)tn * 12800;
            float* dst = xf[(it & 1) ^ 1];
            #pragma unroll
            for (int j = 0; j < 7; j++) {
                int f4 = tid + j * 512;
                if (f4 < 3200) {
                    uint32_t d = (uint32_t)__cvta_generic_to_shared(dst + f4 * 4);
                    asm volatile("cp.async.cg.shared.global [%0], [%1], 16;"
                                 :: "r"(d), "l"(xt2 + f4 * 4) : "memory");
                }
            }
        }
        asm volatile("cp.async.commit_group;" ::: "memory");

        // ---- convert: 0.5*x (smem fp32) -> bf16 Asm ; 0.5*a -> Wext ----
        float av = (tid < 256) ? 0.5f * g_a[(size_t)t * 256 + tid] : 0.f;
        #pragma unroll
        for (int j = 0; j < 7; j++) {
            int f4 = tid + j * 512;
            if (f4 < 3200) {
                float4 w = ((const float4*)xfb)[f4];
                __nv_bfloat162 lo = __floats2bfloat162_rn(0.5f * w.x, 0.5f * w.y);
                __nv_bfloat162 hi = __floats2bfloat162_rn(0.5f * w.z, 0.5f * w.w);
                uint2 u = make_uint2(*(uint32_t*)&lo, *(uint32_t*)&hi);
                *(uint2*)(Asm + (f4 >> 5) * SA + (f4 & 31) * 4) = u;
            }
        }
        if (tid < 256)
            Wext[(tid & 127) * 16 + (tid >> 7)] = __float2bfloat16(av);
        __syncthreads();                        // MMA operands ready

        // ---- MMA: C = (0.5x)@W2^T + onehot@(0.5a)^T ----
        float c[2][4][4] = {};
        #pragma unroll
        for (int ks = 0; ks < 8; ks++) {
            uint32_t A0[4], A1[4], B0[4], B1[4];
            LDSM4(A0, abase + ks * 32);
            LDSM4(A1, abase + 16 * SA * 2 + ks * 32);
            LDSM4(B0, bbase + ks * 32);
            LDSM4(B1, bbase + 16 * SA * 2 + ks * 32);
            MMA16816(c[0][0], A0, B0[0], B0[1]);
            MMA16816(c[0][1], A0, B0[2], B0[3]);
            MMA16816(c[0][2], A0, B1[0], B1[1]);
            MMA16816(c[0][3], A0, B1[2], B1[3]);
            MMA16816(c[1][0], A1, B0[0], B0[1]);
            MMA16816(c[1][1], A1, B0[2], B0[3]);
            MMA16816(c[1][2], A1, B1[0], B1[1]);
            MMA16816(c[1][3], A1, B1[2], B1[3]);
        }
        {   // 9th k-step: per-session bias
            uint32_t B0[4], B1[4];
            LDSM4(B0, ebase);
            LDSM4(B1, ebase + 16 * 32);
            MMA16816(c[0][0], Aext[0], B0[0], B0[1]);
            MMA16816(c[0][1], Aext[0], B0[2], B0[3]);
            MMA16816(c[0][2], Aext[0], B1[0], B1[1]);
            MMA16816(c[0][3], Aext[0], B1[2], B1[3]);
            MMA16816(c[1][0], Aext[1], B0[0], B0[1]);
            MMA16816(c[1][1], Aext[1], B0[2], B0[3]);
            MMA16816(c[1][2], Aext[1], B1[0], B1[1]);
            MMA16816(c[1][3], Aext[1], B1[2], B1[3]);
        }

        // ---- epilogue: e partials = csum + sum 0.5*q*tanh(C) ----
        float pe[2][2] = {};
        #pragma unroll
        for (int ni = 0; ni < 4; ni++) {
            int col = n0 + ni * 8 + (lane & 3) * 2;
            float q0 = qh_sm[col], q1 = qh_sm[col + 1];
            #pragma unroll
            for (int mi = 0; mi < 2; mi++)
                #pragma unroll
                for (int r2 = 0; r2 < 2; r2++) {
                    int row = m0 + mi * 16 + (lane >> 2) + 8 * r2;
                    if (row < 100) {
                        float t0, t1;
                        asm("tanh.approx.f32 %0, %1;" : "=f"(t0) : "f"(c[mi][ni][2 * r2]));
                        asm("tanh.approx.f32 %0, %1;" : "=f"(t1) : "f"(c[mi][ni][2 * r2 + 1]));
                        pe[mi][r2] = fmaf(q0, t0, fmaf(q1, t1, pe[mi][r2]));
                    }
                }
        }
        #pragma unroll
        for (int mi = 0; mi < 2; mi++)
            #pragma unroll
            for (int r2 = 0; r2 < 2; r2++) {
                float vv = pe[mi][r2];
                vv += __shfl_xor_sync(0xffffffffu, vv, 1);
                vv += __shfl_xor_sync(0xffffffffu, vv, 2);
                if ((lane & 3) == 0) {
                    int row = m0 + mi * 16 + (lane >> 2) + 8 * r2;
                    e_part[(warp >> 2) * 128 + row] = vv + csum;
                }
            }
        __syncthreads();

        // ---- per-session softmax over 50 rows (warps 0,1) ----
        if (warp < 2) {
            int rb = warp * 50;
            int i1 = rb + lane;
            bool v2 = lane < 18;
            int i2 = rb + 32 + lane;
            float e1 = e_part[i1] + e_part[128 + i1]
                     + e_part[256 + i1] + e_part[384 + i1] + qb;
            float e2 = v2 ? (e_part[i2] + e_part[128 + i2]
                     + e_part[256 + i2] + e_part[384 + i2] + qb) : -1e30f;
            float m = fmaxf(e1, e2);
            #pragma unroll
            for (int o = 16; o; o >>= 1) m = fmaxf(m, __shfl_xor_sync(0xffffffffu, m, o));
            float z1 = __expf(e1 - m);
            float z2 = v2 ? __expf(e2 - m) : 0.f;
            float s = z1 + z2;
            #pragma unroll
            for (int o = 16; o; o >>= 1) s += __shfl_xor_sync(0xffffffffu, s, o);
            float inv = __frcp_rn(s);
            alpha[i1] = z1 * inv;
            if (v2) alpha[i2] = z2 * inv;
        }
        __syncthreads();

        // ---- pooling from fp32 smem: out[2t+s][col] = sum alpha_j * x_j[col]
        if (tid < 256) {
            int s = tid >> 7, col = tid & 127;
            const float* xr = xfb + s * 6400 + col;
            const float* al = alpha + s * 50;
            float acc = 0.f;
            #pragma unroll 10
            for (int j = 0; j < 50; j++) acc = fmaf(al[j], xr[j * 128], acc);
            out[(size_t)(2 * t + s) * 128 + col] = acc;
        }
        __syncthreads();                        // xfb/alpha reuse next iter
    }
}

extern "C" void kernel_launch(void* const* d_in, const int* in_sizes, int n_in,
                              void* d_out, int out_size)
{
    const float* x   = (const float*)d_in[0];
    const float* W1w = (const float*)d_in[1];
    const float* W1b = (const float*)d_in[2];
    const float* W2w = (const float*)d_in[3];
    const float* W2b = (const float*)d_in[4];
    const float* qw  = (const float*)d_in[5];
    const float* qb  = (const float*)d_in[6];
    const int* last  = (const int*)d_in[8];
    float* out = (float*)d_out;

    int smem1 = 70656;
    cudaFuncSetAttribute(k1_abias, cudaFuncAttributeMaxDynamicSharedMemorySize, smem1);
    cudaFuncSetAttribute(k2_main,  cudaFuncAttributeMaxDynamicSharedMemorySize, K2_SMEM);

    int nsm = 148;
    cudaDeviceGetAttribute(&nsm, cudaDevAttrMultiProcessorCount, 0);

    k1_abias<<<157, 256, smem1>>>(x, W1w, W1b, W2b, last);
    k2_main<<<nsm, 512, K2_SMEM>>>(x, W2w, qw, qb, out);
}

// round 12
// speedup vs baseline: 3.4634x; 1.3398x over previous
#include <cuda_runtime.h>
#include <cuda_bf16.h>
#include <cstdint>

// RecentAttention: N=500000, B=10000 sessions x L=50, H=128.
// K1: g_a[s] = x[last_ixs[s]] @ W1^T + b1 + b2      (bf16 mma.sync, 157 CTAs)
// K2: persistent, 2 CTAs/SM x 256 thr; per tile (2 sessions = 100 rows):
//     C = (0.5x)@W2^T + onehot(sess)@(0.5a)^T   (8+1 k16 steps, 32x64 warp tiles)
//     e = qb + sum 0.5q + sum 0.5q*tanh(C) ; per-session softmax ; pool (L2 x).

#define SA 136                  // smem row stride (bf16 elems), conflict-free
#define NTILE2 5000             // 2 sessions (100 rows) per tile

__device__ float g_a[10000 * 128];

__device__ __forceinline__ void st4bf(__nv_bfloat16* p, float4 v) {
    *(__nv_bfloat162*)p       = __floats2bfloat162_rn(v.x, v.y);
    *(__nv_bfloat162*)(p + 2) = __floats2bfloat162_rn(v.z, v.w);
}

#define MMA16816(C, A, B0, B1)                                              \
    asm volatile("mma.sync.aligned.m16n8k16.row.col.f32.bf16.bf16.f32 "    \
        "{%0,%1,%2,%3}, {%4,%5,%6,%7}, {%8,%9}, {%0,%1,%2,%3};"            \
        : "+f"((C)[0]), "+f"((C)[1]), "+f"((C)[2]), "+f"((C)[3])           \
        : "r"((A)[0]), "r"((A)[1]), "r"((A)[2]), "r"((A)[3]),              \
          "r"(B0), "r"(B1))

#define LDSM4(R, a)                                                         \
    asm volatile("ldmatrix.sync.aligned.m8n8.x4.shared.b16 {%0,%1,%2,%3}, [%4];" \
        : "=r"((R)[0]), "=r"((R)[1]), "=r"((R)[2]), "=r"((R)[3]) : "r"(a))

// ---------------- K1: a[s] = x[last]@W1^T + b1 + b2 (proven R6 path) -------
__device__ __forceinline__ void mma_pass32(uint32_t abase, uint32_t bbase,
                                           float c[2][4][4]) {
    #pragma unroll
    for (int ks = 0; ks < 8; ks++) {
        uint32_t A0[4], A1[4], B0[4], B1[4];
        LDSM4(A0, abase + ks * 32);
        LDSM4(A1, abase + 16 * SA * 2 + ks * 32);
        LDSM4(B0, bbase + ks * 32);
        LDSM4(B1, bbase + 16 * SA * 2 + ks * 32);
        MMA16816(c[0][0], A0, B0[0], B0[1]);
        MMA16816(c[0][1], A0, B0[2], B0[3]);
        MMA16816(c[0][2], A0, B1[0], B1[1]);
        MMA16816(c[0][3], A0, B1[2], B1[3]);
        MMA16816(c[1][0], A1, B0[0], B0[1]);
        MMA16816(c[1][1], A1, B0[2], B0[3]);
        MMA16816(c[1][2], A1, B1[0], B1[1]);
        MMA16816(c[1][3], A1, B1[2], B1[3]);
    }
}

__global__ void __launch_bounds__(256, 1) k1_abias(
    const float* __restrict__ x, const float* __restrict__ W1,
    const float* __restrict__ b1, const float* __restrict__ b2,
    const int* __restrict__ last_ixs)
{
    extern __shared__ char smraw[];
    __nv_bfloat16* Asm = (__nv_bfloat16*)smraw;
    __nv_bfloat16* Wsm = (__nv_bfloat16*)(smraw + 34816);
    int*   li = (int*)(smraw + 69632);
    float* bs = (float*)(smraw + 70144);

    int tid = threadIdx.x, warp = tid >> 5, lane = tid & 31;
    int base = blockIdx.x * 64;
    int valid = min(64, 10000 - base);

    if (tid < 128) {
        li[tid] = (tid < valid) ? last_ixs[base + tid] : 0;
        bs[tid] = b1[tid] + b2[tid];
    }
    #pragma unroll
    for (int j = 0; j < 16; j++) {
        int f4 = tid + j * 256, row = f4 >> 5, c4 = f4 & 31;
        st4bf(Wsm + row * SA + c4 * 4, ((const float4*)W1)[f4]);
    }
    __syncthreads();
    #pragma unroll
    for (int j = 0; j < 16; j++) {
        int f4 = tid + j * 256, row = f4 >> 5, c4 = f4 & 31;
        float4 v = make_float4(0.f, 0.f, 0.f, 0.f);
        if (row < valid) v = ((const float4*)(x + (size_t)li[row] * 128))[c4];
        st4bf(Asm + row * SA + c4 * 4, v);
    }
    __syncthreads();

    int mw = warp >> 1, m0 = mw * 32;
    int q = lane >> 3, r7 = lane & 7;
    uint32_t asm_u = (uint32_t)__cvta_generic_to_shared(Asm);
    uint32_t wsm_u = (uint32_t)__cvta_generic_to_shared(Wsm);
    uint32_t abase = asm_u + 2 * ((m0 + (q & 1) * 8 + r7) * SA + (q >> 1) * 8);

    #pragma unroll
    for (int p = 0; p < 2; p++) {
        int n0 = (warp & 1) * 64 + p * 32;
        uint32_t bbase = wsm_u + 2 * ((n0 + (q >> 1) * 8 + r7) * SA + (q & 1) * 8);
        float c[2][4][4] = {};
        mma_pass32(abase, bbase, c);
        #pragma unroll
        for (int mi = 0; mi < 2; mi++)
            #pragma unroll
            for (int ni = 0; ni < 4; ni++) {
                int col = n0 + ni * 8 + (lane & 3) * 2;
                #pragma unroll
                for (int r2 = 0; r2 < 2; r2++) {
                    int row = m0 + mi * 16 + (lane >> 2) + 8 * r2;
                    if (row < valid) {
                        size_t o = (size_t)(base + row) * 128 + col;
                        g_a[o]     = c[mi][ni][2 * r2]     + bs[col];
                        g_a[o + 1] = c[mi][ni][2 * r2 + 1] + bs[col + 1];
                    }
                }
            }
    }
}

// ---------------- K2: persistent, 2 CTAs/SM, 32x64 warp tiles --------------
// smem: Wsm@0(34816) Asm@34816(34816) Wext@69632(4096) qh@73728(512)
//       e_part@74240(1024) alpha@75264(512)   total 75776
#define K2_SMEM 75776

__global__ void __launch_bounds__(256, 2) k2_main(
    const float* __restrict__ x, const float* __restrict__ W2,
    const float* __restrict__ q, const float* __restrict__ qbp,
    float* __restrict__ out)
{
    extern __shared__ char smraw[];
    __nv_bfloat16* Wsm  = (__nv_bfloat16*)smraw;
    __nv_bfloat16* Asm  = (__nv_bfloat16*)(smraw + 34816);
    __nv_bfloat16* Wext = (__nv_bfloat16*)(smraw + 69632);
    float* qh_sm  = (float*)(smraw + 73728);
    float* e_part = (float*)(smraw + 74240);    // [2][128]
    float* alpha  = (float*)(smraw + 75264);    // [100]

    int tid = threadIdx.x, warp = tid >> 5, lane = tid & 31;
    int m0 = (warp & 3) * 32;                   // warp tile: 32 rows x 64 cols
    int n0 = (warp >> 2) * 64;
    int qq = lane >> 3, r7 = lane & 7;
    float qb = qbp[0];

    #pragma unroll
    for (int j = 0; j < 16; j++) {              // W2 -> bf16 smem (once)
        int f4 = tid + j * 256, row = f4 >> 5, c4 = f4 & 31;
        st4bf(Wsm + row * SA + c4 * 4, ((const float4*)W2)[f4]);
    }
    #pragma unroll
    for (int j = 0; j < 34; j++)                // zero Asm (pad rows stay 0)
        ((uint32_t*)Asm)[tid + j * 256] = 0u;
    #pragma unroll
    for (int j = 0; j < 4; j++)                 // zero Wext (k>=2 stay 0)
        ((uint32_t*)Wext)[tid + j * 256] = 0u;
    if (tid < 128) qh_sm[tid] = 0.5f * q[tid];
    __syncthreads();                            // qh_sm visible before csum

    uint32_t asm_u  = (uint32_t)__cvta_generic_to_shared(Asm);
    uint32_t wsm_u  = (uint32_t)__cvta_generic_to_shared(Wsm);
    uint32_t wext_u = (uint32_t)__cvta_generic_to_shared(Wext);
    uint32_t abase = asm_u + 2 * ((m0 + (qq & 1) * 8 + r7) * SA + (qq >> 1) * 8);
    uint32_t bbase = wsm_u + 2 * ((n0 + (qq >> 1) * 8 + r7) * SA + (qq & 1) * 8);
    uint32_t ebase = wext_u + (n0 + (qq >> 1) * 8 + r7) * 32 + (qq & 1) * 16;

    // one-hot session-indicator A fragments (k=0 -> sess0, k=1 -> sess1)
    int klo = (lane & 3) * 2;
    uint32_t Aext[2][4];
    #pragma unroll
    for (int mi = 0; mi < 2; mi++) {
        #pragma unroll
        for (int h = 0; h < 2; h++) {
            int row = m0 + mi * 16 + (lane >> 2) + 8 * h;
            int sess = (row < 50) ? 0 : (row < 100) ? 1 : -1;
            uint32_t v = 0;
            if (sess == klo)     v |= 0x3F80u;
            if (sess == klo + 1) v |= 0x3F800000u;
            Aext[mi][h] = v;
        }
        Aext[mi][2] = 0u; Aext[mi][3] = 0u;
    }

    float csum = 0.f;                           // sum of 0.5*q over warp's cols
    #pragma unroll
    for (int g = 0; g < 16; g++) {
        float4 qv = *(const float4*)(qh_sm + n0 + g * 4);
        csum += qv.x + qv.y + qv.z + qv.w;
    }

    for (int t = blockIdx.x; t < NTILE2; t += gridDim.x) {
        const float* xt = x + (size_t)t * 12800;

        // ---- fill: x tile -> 0.5x bf16 Asm (batched LDG) ; 0.5a -> Wext ----
        float4 v[13];
        #pragma unroll
        for (int j = 0; j < 13; j++) {
            int f4 = tid + j * 256;
            if (f4 < 3200) v[j] = ((const float4*)xt)[f4];
        }
        float av = 0.5f * g_a[(size_t)t * 256 + tid];
        #pragma unroll
        for (int j = 0; j < 13; j++) {
            int f4 = tid + j * 256;
            if (f4 < 3200) {
                float4 w = v[j];
                w.x *= 0.5f; w.y *= 0.5f; w.z *= 0.5f; w.w *= 0.5f;
                st4bf(Asm + (f4 >> 5) * SA + (f4 & 31) * 4, w);
            }
        }
        Wext[(tid & 127) * 16 + (tid >> 7)] = __float2bfloat16(av);
        __syncthreads();                        // MMA operands ready

        // ---- MMA: C = (0.5x)@W2^T + onehot@(0.5a)^T  (32x64 single pass) ----
        float c[2][8][4] = {};
        #pragma unroll
        for (int ks = 0; ks < 8; ks++) {
            uint32_t A0[4], A1[4], B0[4], B1[4], B2[4], B3[4];
            LDSM4(A0, abase + ks * 32);
            LDSM4(A1, abase + 16 * SA * 2 + ks * 32);
            LDSM4(B0, bbase + ks * 32);
            LDSM4(B1, bbase + 16 * SA * 2 + ks * 32);
            LDSM4(B2, bbase + 32 * SA * 2 + ks * 32);
            LDSM4(B3, bbase + 48 * SA * 2 + ks * 32);
            MMA16816(c[0][0], A0, B0[0], B0[1]); MMA16816(c[1][0], A1, B0[0], B0[1]);
            MMA16816(c[0][1], A0, B0[2], B0[3]); MMA16816(c[1][1], A1, B0[2], B0[3]);
            MMA16816(c[0][2], A0, B1[0], B1[1]); MMA16816(c[1][2], A1, B1[0], B1[1]);
            MMA16816(c[0][3], A0, B1[2], B1[3]); MMA16816(c[1][3], A1, B1[2], B1[3]);
            MMA16816(c[0][4], A0, B2[0], B2[1]); MMA16816(c[1][4], A1, B2[0], B2[1]);
            MMA16816(c[0][5], A0, B2[2], B2[3]); MMA16816(c[1][5], A1, B2[2], B2[3]);
            MMA16816(c[0][6], A0, B3[0], B3[1]); MMA16816(c[1][6], A1, B3[0], B3[1]);
            MMA16816(c[0][7], A0, B3[2], B3[3]); MMA16816(c[1][7], A1, B3[2], B3[3]);
        }
        {   // 9th k-step: per-session bias
            uint32_t B0[4], B1[4], B2[4], B3[4];
            LDSM4(B0, ebase);
            LDSM4(B1, ebase + 16 * 32);
            LDSM4(B2, ebase + 32 * 32);
            LDSM4(B3, ebase + 48 * 32);
            MMA16816(c[0][0], Aext[0], B0[0], B0[1]); MMA16816(c[1][0], Aext[1], B0[0], B0[1]);
            MMA16816(c[0][1], Aext[0], B0[2], B0[3]); MMA16816(c[1][1], Aext[1], B0[2], B0[3]);
            MMA16816(c[0][2], Aext[0], B1[0], B1[1]); MMA16816(c[1][2], Aext[1], B1[0], B1[1]);
            MMA16816(c[0][3], Aext[0], B1[2], B1[3]); MMA16816(c[1][3], Aext[1], B1[2], B1[3]);
            MMA16816(c[0][4], Aext[0], B2[0], B2[1]); MMA16816(c[1][4], Aext[1], B2[0], B2[1]);
            MMA16816(c[0][5], Aext[0], B2[2], B2[3]); MMA16816(c[1][5], Aext[1], B2[2], B2[3]);
            MMA16816(c[0][6], Aext[0], B3[0], B3[1]); MMA16816(c[1][6], Aext[1], B3[0], B3[1]);
            MMA16816(c[0][7], Aext[0], B3[2], B3[3]); MMA16816(c[1][7], Aext[1], B3[2], B3[3]);
        }

        // ---- epilogue: e partials = csum + sum 0.5*q*tanh(C) ----
        float pe[2][2] = {};
        #pragma unroll
        for (int ni = 0; ni < 8; ni++) {
            int col = n0 + ni * 8 + (lane & 3) * 2;
            float q0 = qh_sm[col], q1 = qh_sm[col + 1];
            #pragma unroll
            for (int mi = 0; mi < 2; mi++)
                #pragma unroll
                for (int r2 = 0; r2 < 2; r2++) {
                    int row = m0 + mi * 16 + (lane >> 2) + 8 * r2;
                    if (row < 100) {
                        float t0, t1;
                        asm("tanh.approx.f32 %0, %1;" : "=f"(t0) : "f"(c[mi][ni][2 * r2]));
                        asm("tanh.approx.f32 %0, %1;" : "=f"(t1) : "f"(c[mi][ni][2 * r2 + 1]));
                        pe[mi][r2] = fmaf(q0, t0, fmaf(q1, t1, pe[mi][r2]));
                    }
                }
        }
        #pragma unroll
        for (int mi = 0; mi < 2; mi++)
            #pragma unroll
            for (int r2 = 0; r2 < 2; r2++) {
                float vv = pe[mi][r2];
                vv += __shfl_xor_sync(0xffffffffu, vv, 1);
                vv += __shfl_xor_sync(0xffffffffu, vv, 2);
                if ((lane & 3) == 0) {
                    int row = m0 + mi * 16 + (lane >> 2) + 8 * r2;
                    e_part[(warp >> 2) * 128 + row] = vv + csum;
                }
            }
        __syncthreads();

        // ---- per-session softmax over 50 rows (warps 0,1) ----
        if (warp < 2) {
            int rb = warp * 50;
            int i1 = rb + lane;
            bool v2 = lane < 18;
            int i2 = rb + 32 + lane;
            float e1 = e_part[i1] + e_part[128 + i1] + qb;
            float e2 = v2 ? (e_part[i2] + e_part[128 + i2] + qb) : -1e30f;
            float m = fmaxf(e1, e2);
            #pragma unroll
            for (int o = 16; o; o >>= 1) m = fmaxf(m, __shfl_xor_sync(0xffffffffu, m, o));
            float z1 = __expf(e1 - m);
            float z2 = v2 ? __expf(e2 - m) : 0.f;
            float s = z1 + z2;
            #pragma unroll
            for (int o = 16; o; o >>= 1) s += __shfl_xor_sync(0xffffffffu, s, o);
            float inv = __frcp_rn(s);
            alpha[i1] = z1 * inv;
            if (v2) alpha[i2] = z2 * inv;
        }
        __syncthreads();

        // ---- pooling: out[2t+s][col] = sum_j alpha_j * x_j[col] (fp32, L2) ----
        int s = tid >> 7, col = tid & 127;
        const float* xr = xt + s * 6400 + col;
        const float* al = alpha + s * 50;
        float acc = 0.f;
        #pragma unroll 10
        for (int j = 0; j < 50; j++) acc = fmaf(al[j], xr[j * 128], acc);
        out[(size_t)(2 * t + s) * 128 + col] = acc;
        __syncthreads();                        // alpha/Asm safe to overwrite
    }
}

extern "C" void kernel_launch(void* const* d_in, const int* in_sizes, int n_in,
                              void* d_out, int out_size)
{
    const float* x   = (const float*)d_in[0];
    const float* W1w = (const float*)d_in[1];
    const float* W1b = (const float*)d_in[2];
    const float* W2w = (const float*)d_in[3];
    const float* W2b = (const float*)d_in[4];
    const float* qw  = (const float*)d_in[5];
    const float* qb  = (const float*)d_in[6];
    const int* last  = (const int*)d_in[8];
    float* out = (float*)d_out;

    int smem1 = 70656;
    cudaFuncSetAttribute(k1_abias, cudaFuncAttributeMaxDynamicSharedMemorySize, smem1);
    cudaFuncSetAttribute(k2_main,  cudaFuncAttributeMaxDynamicSharedMemorySize, K2_SMEM);

    int nsm = 148;
    cudaDeviceGetAttribute(&nsm, cudaDevAttrMultiProcessorCount, 0);

    k1_abias<<<157, 256, smem1>>>(x, W1w, W1b, W2b, last);
    k2_main<<<2 * nsm, 256, K2_SMEM>>>(x, W2w, qw, qb, out);
}